// round 6
// baseline (speedup 1.0000x reference)
#include <cuda_runtime.h>
#include <math.h>

#define NN 10000
#define EE 160000
#define HH 512
#define ED 16
#define LN_EPS 1e-5f
#define EDGE_SCALE 0.1f

// ---------------- scratch (device globals; no allocation allowed) ------------
__device__ float g_pm[NN * HH];     // h @ msg_w1[0:512] + msg_b1
__device__ float g_aggG[NN * HH];   // segment-sum of gelu(pre)
__device__ float g_act[NN * HH];    // gelu(U1pre)
__device__ float g_h2[NN * HH];     // h + act@upd_w2 + upd_b2 (pre-LN)
__device__ float g_As[NN * ED];
__device__ float g_Ad[NN * ED];
__device__ float g_gs[NN];
__device__ float g_gd[NN];
__device__ float g_deg[NN];
__device__ float g_Wcomb[HH * HH];  // msg_w2 @ upd_w1[512:1024]
__device__ float g_bvec2[HH];       // msg_b2 @ upd_w1[512:1024]

// ---------------- helpers ----------------------------------------------------
__device__ __forceinline__ float gelu_exact(float x) {
    return x * normcdff(x);  // x * Phi(x), matches jax gelu(approximate=False)
}

__device__ __forceinline__ float warpSum(float v) {
    #pragma unroll
    for (int o = 16; o >= 1; o >>= 1)
        v += __shfl_xor_sync(0xffffffffu, v, o);
    return v;
}

// ---------------- zero-fill (replaces cudaMemsetAsync) ------------------------
__global__ void zero_kernel() {
    size_t i = (size_t)blockIdx.x * blockDim.x + threadIdx.x;
    size_t tot = (size_t)NN * HH;
    if (i < tot) g_aggG[i] = 0.f;
    if (i < NN)  g_deg[i]  = 0.f;
}

// ---------------- generic fused SGEMM ----------------------------------------
// C[M x Ncols] = [A1 | A2] @ [B1 ; B2]  (+ bias[n]) (+ rowscale[m]*rowvec[n])
//               (+ addsrc[m][n]) ; optional gelu.  A row-major, B row-major.
#define BM 128
#define BN 128
#define BK 16

__global__ __launch_bounds__(256, 2)
void sgemm_fused(int M, int Ncols, int K1, int K2,
                 const float* __restrict__ A1, int lda1,
                 const float* __restrict__ B1, int ldb1,
                 const float* __restrict__ A2, int lda2,
                 const float* __restrict__ B2, int ldb2,
                 const float* __restrict__ bias,
                 const float* __restrict__ rowscale,
                 const float* __restrict__ rowvec,
                 const float* __restrict__ addsrc,
                 int do_gelu,
                 float* __restrict__ C)
{
    __shared__ float sA[BK][BM];
    __shared__ float sB[BK][BN];

    const int tid = threadIdx.x;
    const int n0 = blockIdx.x * BN;
    const int m0 = blockIdx.y * BM;
    const int ty = tid >> 4;     // 0..15  -> rows ty*8..ty*8+7
    const int tx = tid & 15;     // 0..15  -> cols tx*8..tx*8+7

    float acc[8][8];
    #pragma unroll
    for (int i = 0; i < 8; i++)
        #pragma unroll
        for (int j = 0; j < 8; j++) acc[i][j] = 0.f;

    const int Ktot = K1 + K2;
    for (int kt = 0; kt < Ktot; kt += BK) {
        const float* A; const float* Bp; int lda, ldb, kl;
        if (kt < K1) { A = A1; Bp = B1; lda = lda1; ldb = ldb1; kl = kt; }
        else         { A = A2; Bp = B2; lda = lda2; ldb = ldb2; kl = kt - K1; }

        // load A tile (BM x BK), store transposed sA[k][m]
        #pragma unroll
        for (int t = 0; t < 2; t++) {
            int idx = tid + t * 256;            // 0..511 float4s
            int r   = idx >> 2;                 // 0..127
            int c4  = (idx & 3) * 4;            // 0,4,8,12
            int m   = m0 + r;
            float4 v = make_float4(0.f, 0.f, 0.f, 0.f);
            if (m < M) v = *(const float4*)(A + (size_t)m * lda + kl + c4);
            sA[c4 + 0][r] = v.x; sA[c4 + 1][r] = v.y;
            sA[c4 + 2][r] = v.z; sA[c4 + 3][r] = v.w;
        }
        // load B tile (BK x BN)
        #pragma unroll
        for (int t = 0; t < 2; t++) {
            int idx = tid + t * 256;
            int r   = idx >> 5;                 // 0..15
            int c4  = (idx & 31) * 4;           // 0..124
            float4 v = *(const float4*)(Bp + (size_t)(kl + r) * ldb + n0 + c4);
            *(float4*)&sB[r][c4] = v;
        }
        __syncthreads();

        #pragma unroll
        for (int kk = 0; kk < BK; kk++) {
            float ar[8], br[8];
            *(float4*)(ar)     = *(const float4*)&sA[kk][ty * 8];
            *(float4*)(ar + 4) = *(const float4*)&sA[kk][ty * 8 + 4];
            *(float4*)(br)     = *(const float4*)&sB[kk][tx * 8];
            *(float4*)(br + 4) = *(const float4*)&sB[kk][tx * 8 + 4];
            #pragma unroll
            for (int i = 0; i < 8; i++)
                #pragma unroll
                for (int j = 0; j < 8; j++)
                    acc[i][j] += ar[i] * br[j];
        }
        __syncthreads();
    }

    #pragma unroll
    for (int i = 0; i < 8; i++) {
        int m = m0 + ty * 8 + i;
        if (m >= M) continue;
        float rs = rowscale ? rowscale[m] : 0.f;
        #pragma unroll
        for (int j = 0; j < 8; j++) {
            int n = n0 + tx * 8 + j;
            float v = acc[i][j];
            if (bias)   v += bias[n];
            if (rowvec) v += rs * rowvec[n];
            if (addsrc) v += addsrc[(size_t)m * Ncols + n];
            if (do_gelu) v = gelu_exact(v);
            C[(size_t)m * Ncols + n] = v;
        }
    }
}

// Thin wrappers that bind device-global scratch as operands (no host-side
// symbol-address API needed). sel codes pick the operand set.
__global__ __launch_bounds__(256, 2)
void sgemm_pm(const float* __restrict__ h, const float* __restrict__ msg_w1,
              const float* __restrict__ msg_b1)
{
    // forwarded manually: pm = h @ msg_w1[0:512] + msg_b1
    // (duplicate of sgemm_fused body via device-side call is avoided; instead
    //  we just launch sgemm_fused directly from host with global pointers
    //  resolved in device code — see launcher kernels below.)
}

// Pointer table filled on device, consumed by host? Not allowed. Instead:
// we give sgemm_fused variants that hard-bind globals.

__global__ __launch_bounds__(256, 2)
void sgemm_g(int which, int M, int Ncols, int K1, int K2,
             const float* __restrict__ X1, int lda1,
             const float* __restrict__ W1, int ldb1,
             const float* __restrict__ bias_in,
             const float* __restrict__ addsrc_in,
             int do_gelu)
{
    // which: 0 pm=h@msgw1+b          (C=g_pm)
    //        1 Wcomb=msgw2@updw1hi   (C=g_Wcomb)
    //        2 act=gelu(h@updw1 + aggG@Wcomb + b + deg*bvec2) (C=g_act)
    //        3 h2 = X1@updw2 + b + addsrc(h)                  (C=g_h2)
    const float* A1 = X1; const float* B1 = W1;
    const float* A2 = nullptr; const float* B2 = nullptr;
    int lda2 = HH, ldb2 = HH;
    const float* bias = bias_in;
    const float* rowscale = nullptr; const float* rowvec = nullptr;
    const float* addsrc = addsrc_in;
    float* C;
    if (which == 0)      C = g_pm;
    else if (which == 1) C = g_Wcomb;
    else if (which == 2) { C = g_act; A2 = g_aggG; B2 = g_Wcomb;
                           rowscale = g_deg; rowvec = g_bvec2; }
    else                 C = g_h2;

    // ------- body identical to sgemm_fused -------
    __shared__ float sA[BK][BM];
    __shared__ float sB[BK][BN];
    const int tid = threadIdx.x;
    const int n0 = blockIdx.x * BN;
    const int m0 = blockIdx.y * BM;
    const int ty = tid >> 4;
    const int tx = tid & 15;

    float acc[8][8];
    #pragma unroll
    for (int i = 0; i < 8; i++)
        #pragma unroll
        for (int j = 0; j < 8; j++) acc[i][j] = 0.f;

    const int Ktot = K1 + K2;
    for (int kt = 0; kt < Ktot; kt += BK) {
        const float* A; const float* Bp; int lda, ldb, kl;
        if (kt < K1) { A = A1; Bp = B1; lda = lda1; ldb = ldb1; kl = kt; }
        else         { A = A2; Bp = B2; lda = lda2; ldb = ldb2; kl = kt - K1; }

        #pragma unroll
        for (int t = 0; t < 2; t++) {
            int idx = tid + t * 256;
            int r   = idx >> 2;
            int c4  = (idx & 3) * 4;
            int m   = m0 + r;
            float4 v = make_float4(0.f, 0.f, 0.f, 0.f);
            if (m < M) v = *(const float4*)(A + (size_t)m * lda + kl + c4);
            sA[c4 + 0][r] = v.x; sA[c4 + 1][r] = v.y;
            sA[c4 + 2][r] = v.z; sA[c4 + 3][r] = v.w;
        }
        #pragma unroll
        for (int t = 0; t < 2; t++) {
            int idx = tid + t * 256;
            int r   = idx >> 5;
            int c4  = (idx & 31) * 4;
            float4 v = *(const float4*)(Bp + (size_t)(kl + r) * ldb + n0 + c4);
            *(float4*)&sB[r][c4] = v;
        }
        __syncthreads();

        #pragma unroll
        for (int kk = 0; kk < BK; kk++) {
            float ar[8], br[8];
            *(float4*)(ar)     = *(const float4*)&sA[kk][ty * 8];
            *(float4*)(ar + 4) = *(const float4*)&sA[kk][ty * 8 + 4];
            *(float4*)(br)     = *(const float4*)&sB[kk][tx * 8];
            *(float4*)(br + 4) = *(const float4*)&sB[kk][tx * 8 + 4];
            #pragma unroll
            for (int i = 0; i < 8; i++)
                #pragma unroll
                for (int j = 0; j < 8; j++)
                    acc[i][j] += ar[i] * br[j];
        }
        __syncthreads();
    }

    #pragma unroll
    for (int i = 0; i < 8; i++) {
        int m = m0 + ty * 8 + i;
        if (m >= M) continue;
        float rs = rowscale ? rowscale[m] : 0.f;
        #pragma unroll
        for (int j = 0; j < 8; j++) {
            int n = n0 + tx * 8 + j;
            float v = acc[i][j];
            if (bias)   v += bias[n];
            if (rowvec) v += rs * rowvec[n];
            if (addsrc) v += addsrc[(size_t)m * Ncols + n];
            if (do_gelu) v = gelu_exact(v);
            C[(size_t)m * Ncols + n] = v;
        }
    }
}

// special: which==3 needs A1 = g_act (a global). Use a flag: if X1==nullptr, A1=g_act.
__global__ __launch_bounds__(256, 2)
void sgemm_h2(const float* __restrict__ updw2, const float* __restrict__ updb2,
              const float* __restrict__ h)
{
    const float* A1 = g_act; const float* B1 = updw2;
    const int M = NN, Ncols = HH, K1 = HH;
    float* C = g_h2;

    __shared__ float sA[BK][BM];
    __shared__ float sB[BK][BN];
    const int tid = threadIdx.x;
    const int n0 = blockIdx.x * BN;
    const int m0 = blockIdx.y * BM;
    const int ty = tid >> 4;
    const int tx = tid & 15;

    float acc[8][8];
    #pragma unroll
    for (int i = 0; i < 8; i++)
        #pragma unroll
        for (int j = 0; j < 8; j++) acc[i][j] = 0.f;

    for (int kt = 0; kt < K1; kt += BK) {
        #pragma unroll
        for (int t = 0; t < 2; t++) {
            int idx = tid + t * 256;
            int r   = idx >> 2;
            int c4  = (idx & 3) * 4;
            int m   = m0 + r;
            float4 v = make_float4(0.f, 0.f, 0.f, 0.f);
            if (m < M) v = *(const float4*)(A1 + (size_t)m * HH + kt + c4);
            sA[c4 + 0][r] = v.x; sA[c4 + 1][r] = v.y;
            sA[c4 + 2][r] = v.z; sA[c4 + 3][r] = v.w;
        }
        #pragma unroll
        for (int t = 0; t < 2; t++) {
            int idx = tid + t * 256;
            int r   = idx >> 5;
            int c4  = (idx & 31) * 4;
            float4 v = *(const float4*)(B1 + (size_t)(kt + r) * HH + n0 + c4);
            *(float4*)&sB[r][c4] = v;
        }
        __syncthreads();
        #pragma unroll
        for (int kk = 0; kk < BK; kk++) {
            float ar[8], br[8];
            *(float4*)(ar)     = *(const float4*)&sA[kk][ty * 8];
            *(float4*)(ar + 4) = *(const float4*)&sA[kk][ty * 8 + 4];
            *(float4*)(br)     = *(const float4*)&sB[kk][tx * 8];
            *(float4*)(br + 4) = *(const float4*)&sB[kk][tx * 8 + 4];
            #pragma unroll
            for (int i = 0; i < 8; i++)
                #pragma unroll
                for (int j = 0; j < 8; j++)
                    acc[i][j] += ar[i] * br[j];
        }
        __syncthreads();
    }

    #pragma unroll
    for (int i = 0; i < 8; i++) {
        int m = m0 + ty * 8 + i;
        if (m >= M) continue;
        #pragma unroll
        for (int j = 0; j < 8; j++) {
            int n = n0 + tx * 8 + j;
            C[(size_t)m * HH + n] = acc[i][j] + updb2[n] + h[(size_t)m * HH + n];
        }
    }
}

// ---------------- per-node small precomputes ---------------------------------
__global__ __launch_bounds__(256)
void node_small(const float* __restrict__ h, const float* __restrict__ W,
                const float* __restrict__ eg, int which)  // 0 -> As/gs, 1 -> Ad/gd
{
    float* outA = which ? g_Ad : g_As;
    float* outg = which ? g_gd : g_gs;

    __shared__ float sWT[16][512];
    __shared__ float sEg[512];
    int tid = threadIdx.x;
    for (int idx = tid; idx < 512 * 16; idx += 256) {
        int r = idx >> 4, c = idx & 15;
        sWT[c][r] = W[idx];
    }
    for (int idx = tid; idx < 512; idx += 256) sEg[idx] = eg[idx];
    __syncthreads();

    int warp = tid >> 5, lane = tid & 31;
    int n = blockIdx.x * 8 + warp;
    if (n >= NN) return;
    const float* hr = h + (size_t)n * 512;
    float hreg[16];
    #pragma unroll
    for (int k = 0; k < 16; k++) hreg[k] = hr[lane + 32 * k];

    float ag = 0.f;
    #pragma unroll
    for (int k = 0; k < 16; k++) ag += hreg[k] * sEg[lane + 32 * k];
    ag = warpSum(ag);
    if (lane == 0) outg[n] = ag;

    float myA = 0.f;
    #pragma unroll
    for (int col = 0; col < 16; col++) {
        float acc = 0.f;
        #pragma unroll
        for (int k = 0; k < 16; k++) acc += hreg[k] * sWT[col][lane + 32 * k];
        acc = warpSum(acc);
        if (lane == col) myA = acc;
    }
    if (lane < 16) outA[(size_t)n * 16 + lane] = myA;
}

// ---------------- degree ------------------------------------------------------
__global__ void deg_kernel(const int* __restrict__ ei) {
    int e = blockIdx.x * blockDim.x + threadIdx.x;
    if (e < EE) atomicAdd(&g_deg[ei[EE + e]], 1.0f);
}

// ---------------- fused edge kernel ------------------------------------------
__global__ __launch_bounds__(256)
void edge_kernel(const float* __restrict__ ea, const int* __restrict__ ei,
                 const float* __restrict__ msg_w1,
                 const float* __restrict__ em_w1, const float* __restrict__ em_b1,
                 const float* __restrict__ em_w2, const float* __restrict__ em_b2,
                 const float* __restrict__ eg_w,  const float* __restrict__ eg_b,
                 const float* __restrict__ en_g,  const float* __restrict__ en_b,
                 float* __restrict__ e_new_out)
{
    __shared__ float sWm[16][512];   // msg_w1 rows 512..527
    __shared__ float sE1[16][16];    // em_w1 rows 1024..1039
    __shared__ float sE2[16][16];    // em_w2
    __shared__ float sEge[16], sB1[16], sB2[16], sGam[16], sBet[16];
    __shared__ float s_egb;

    int tid = threadIdx.x;
    for (int idx = tid; idx < (16 * 512) / 4; idx += 256)
        ((float4*)sWm)[idx] = ((const float4*)(msg_w1 + 512 * 512))[idx];
    if (tid < 256) {
        sE1[tid >> 4][tid & 15] = em_w1[1024 * 16 + tid];
        sE2[tid >> 4][tid & 15] = em_w2[tid];
    }
    if (tid < 16) {
        sEge[tid] = eg_w[1024 + tid];
        sB1[tid]  = em_b1[tid];
        sB2[tid]  = em_b2[tid];
        sGam[tid] = en_g[tid];
        sBet[tid] = en_b[tid];
    }
    if (tid == 0) s_egb = eg_b[0];
    __syncthreads();

    const int warp = tid >> 5, lane = tid & 31;
    const int l16 = lane & 15;

    #pragma unroll 1
    for (int t = 0; t < 4; t++) {
        int e = blockIdx.x * 32 + warp * 4 + t;
        if (e >= EE) continue;
        int src = ei[e];
        int dst = ei[EE + e];

        float a = (lane < 16) ? ea[(size_t)e * 16 + lane] : 0.f;

        float t16 = 0.f;
        if (lane < 16)
            t16 = g_As[(size_t)src * 16 + lane] + g_Ad[(size_t)dst * 16 + lane] + sB1[lane];
        float gp = (lane < 16) ? a * sEge[lane] : 0.f;
        #pragma unroll
        for (int c = 0; c < 16; c++) {
            float ac = __shfl_sync(0xffffffffu, a, c);
            t16 += ac * sE1[c][l16];
        }
        float glog = warpSum(gp) + g_gs[src] + g_gd[dst] + s_egb;
        float gate = 1.f / (1.f + expf(-glog));

        float gact = (lane < 16) ? gelu_exact(t16) : 0.f;
        float dl = (lane < 16) ? sB2[lane] : 0.f;
        #pragma unroll
        for (int c = 0; c < 16; c++) {
            float gc = __shfl_sync(0xffffffffu, gact, c);
            dl += gc * sE2[c][l16];
        }

        float epre = (lane < 16) ? (a + EDGE_SCALE * gate * dl) : 0.f;
        float mu = warpSum(epre) * (1.f / 16.f);
        float dx = (lane < 16) ? (epre - mu) : 0.f;
        float var = warpSum(dx * dx) * (1.f / 16.f);
        float inv = rsqrtf(var + LN_EPS);
        float en = dx * inv * sGam[l16] + sBet[l16];
        if (lane < 16) e_new_out[(size_t)e * 16 + lane] = en;

        float enreg = (lane < 16) ? en : 0.f;
        float en_all[16];
        #pragma unroll
        for (int c = 0; c < 16; c++)
            en_all[c] = __shfl_sync(0xffffffffu, enreg, c);

        const float* pmrow = g_pm + (size_t)src * 512;
        float* aggrow = g_aggG + (size_t)dst * 512;
        #pragma unroll
        for (int k = 0; k < 16; k++) {
            int j = lane + 32 * k;
            float acc = pmrow[j];
            #pragma unroll
            for (int c = 0; c < 16; c++) acc += en_all[c] * sWm[c][j];
            acc = gelu_exact(acc);
            atomicAdd(&aggrow[j], acc);
        }
    }
}

// ---------------- bvec2 = msg_b2 @ upd_w1[512:1024] --------------------------
__global__ void bvec2_kernel(const float* __restrict__ msg_b2,
                             const float* __restrict__ upd_w1)
{
    int j = blockIdx.x * blockDim.x + threadIdx.x;
    if (j >= HH) return;
    float acc = 0.f;
    for (int k = 0; k < HH; k++)
        acc += msg_b2[k] * upd_w1[(size_t)(512 + k) * 512 + j];
    g_bvec2[j] = acc;
}

// ---------------- node LayerNorm ---------------------------------------------
__global__ __launch_bounds__(256)
void ln_node(const float* __restrict__ g, const float* __restrict__ b,
             float* __restrict__ out)
{
    int warp = (blockIdx.x * blockDim.x + threadIdx.x) >> 5;
    int lane = threadIdx.x & 31;
    if (warp >= NN) return;
    const float* row = g_h2 + (size_t)warp * 512;
    float vals[16];
    float s = 0.f;
    #pragma unroll
    for (int k = 0; k < 16; k++) { vals[k] = row[lane + 32 * k]; s += vals[k]; }
    s = warpSum(s);
    float mu = s * (1.f / 512.f);
    float vs = 0.f;
    #pragma unroll
    for (int k = 0; k < 16; k++) { float d = vals[k] - mu; vs += d * d; }
    vs = warpSum(vs);
    float inv = rsqrtf(vs * (1.f / 512.f) + LN_EPS);
    float* orow = out + (size_t)warp * 512;
    #pragma unroll
    for (int k = 0; k < 16; k++) {
        int j = lane + 32 * k;
        orow[j] = (vals[k] - mu) * inv * g[j] + b[j];
    }
}

// ---------------- launch: kernel launches ONLY -------------------------------
extern "C" void kernel_launch(void* const* d_in, const int* in_sizes, int n_in,
                              void* d_out, int out_size)
{
    const float* h        = (const float*)d_in[0];
    const float* ea       = (const float*)d_in[1];
    const float* msg_w1   = (const float*)d_in[2];
    const float* msg_b1   = (const float*)d_in[3];
    const float* msg_w2   = (const float*)d_in[4];
    const float* msg_b2   = (const float*)d_in[5];
    const float* upd_w1   = (const float*)d_in[6];
    const float* upd_b1   = (const float*)d_in[7];
    const float* upd_w2   = (const float*)d_in[8];
    const float* upd_b2   = (const float*)d_in[9];
    const float* norm_g   = (const float*)d_in[10];
    const float* norm_b   = (const float*)d_in[11];
    const float* em_w1    = (const float*)d_in[12];
    const float* em_b1    = (const float*)d_in[13];
    const float* em_w2    = (const float*)d_in[14];
    const float* em_b2    = (const float*)d_in[15];
    const float* eg_w     = (const float*)d_in[16];
    const float* eg_b     = (const float*)d_in[17];
    const float* en_g     = (const float*)d_in[18];
    const float* en_b     = (const float*)d_in[19];
    const int*   ei       = (const int*)d_in[20];

    float* out    = (float*)d_out;
    float* h_out  = out;                   // N*H
    float* e_out  = out + (size_t)NN * HH; // E*ED

    // zero aggG + deg
    {
        size_t tot = (size_t)NN * HH;
        zero_kernel<<<(unsigned)((tot + 255) / 256), 256>>>();
    }

    // node precomputes for the edge MLP / gate
    node_small<<<NN / 8, 256>>>(h, em_w1,            eg_w,       0);
    node_small<<<NN / 8, 256>>>(h, em_w1 + 512 * 16, eg_w + 512, 1);

    // pm = h @ msg_w1[0:512] + msg_b1
    {
        dim3 grid(HH / BN, (NN + BM - 1) / BM);
        sgemm_g<<<grid, 256>>>(0, NN, HH, HH, 0, h, HH, msg_w1, HH,
                               msg_b1, nullptr, 0);
    }

    deg_kernel<<<(EE + 255) / 256, 256>>>(ei);

    // fused edge phase
    edge_kernel<<<EE / 32, 256>>>(ea, ei, msg_w1,
                                  em_w1, em_b1, em_w2, em_b2,
                                  eg_w, eg_b, en_g, en_b,
                                  e_out);

    // Wcomb = msg_w2 @ upd_w1[512:1024]
    {
        dim3 grid(HH / BN, HH / BM);
        sgemm_g<<<grid, 256>>>(1, HH, HH, HH, 0, msg_w2, HH,
                               upd_w1 + 512 * 512, HH, nullptr, nullptr, 0);
    }
    bvec2_kernel<<<2, 256>>>(msg_b2, upd_w1);

    // act = gelu(h @ upd_w1[0:512] + aggG @ Wcomb + upd_b1 + deg*bvec2)
    {
        dim3 grid(HH / BN, (NN + BM - 1) / BM);
        sgemm_g<<<grid, 256>>>(2, NN, HH, HH, HH, h, HH, upd_w1, HH,
                               upd_b1, nullptr, 1);
    }

    // h2 = act @ upd_w2 + upd_b2 + h
    {
        dim3 grid(HH / BN, (NN + BM - 1) / BM);
        sgemm_h2<<<grid, 256>>>(upd_w2, upd_b2, h);
    }

    // h_out = LN(h2)
    ln_node<<<NN / 8, 256>>>(norm_g, norm_b, h_out);
}